// round 16
// baseline (speedup 1.0000x reference)
#include <cuda_runtime.h>

typedef unsigned long long u64;

// Binary expansion of 1/(2*pi), preceded by 160 zero bits of padding so the
// window index p0 = e + 10 is always >= 0 for fp32 exponents of a = x*pi.
__constant__ unsigned c_PH[14] = {
    0u, 0u, 0u, 0u, 0u,
    0x28BE60DBu, 0x9391054Au, 0x7F09D5F4u, 0x7D4D3770u,
    0x36D8A566u, 0x4F10E410u, 0x7F9458EAu, 0xF7AEF158u, 0x6DC91B8Eu
};

// ---- packed f32x2 helpers (sm_103a FFMA2 path) -----------------------------
__device__ __forceinline__ void fma2(u64 &acc, u64 w, u64 xx) {
    asm("fma.rn.f32x2 %0, %1, %2, %0;" : "+l"(acc) : "l"(w), "l"(xx));
}
__device__ __forceinline__ u64 dup2(float s) {
    u64 r; asm("mov.b64 %0, {%1, %1};" : "=l"(r) : "f"(s)); return r;
}
__device__ __forceinline__ u64 pack2(float lo, float hi) {
    u64 r; asm("mov.b64 %0, {%1, %2};" : "=l"(r) : "f"(lo), "f"(hi)); return r;
}
__device__ __forceinline__ void unpack2(u64 v, float &lo, float &hi) {
    asm("mov.b64 {%0, %1}, %2;" : "=f"(lo), "=f"(hi) : "l"(v));
}

// 64-wide row FMA for THREE points sharing one weight-row load.
// 16 LDS.128 feed 96 FFMA2 (was 64 at 2pt): better latency cover per load.
__device__ __forceinline__ void row_fma3(u64 *a0, u64 *a1, u64 *a2,
                                         const float *wrow,
                                         u64 x0, u64 x1, u64 x2) {
    const ulonglong2 *p = reinterpret_cast<const ulonglong2 *>(wrow);
#pragma unroll
    for (int q = 0; q < 16; ++q) {
        ulonglong2 w = p[q];
        fma2(a0[2 * q + 0], w.x, x0);
        fma2(a0[2 * q + 1], w.y, x0);
        fma2(a1[2 * q + 0], w.x, x1);
        fma2(a1[2 * q + 1], w.y, x1);
        fma2(a2[2 * q + 0], w.x, x2);
        fma2(a2[2 * q + 1], w.y, x2);
    }
}
// Single-point 64-wide row FMA (unit pairs packed in f32x2) for pass B.
__device__ __forceinline__ void row_fma1(u64 *a, const float *wrow, u64 xx) {
    const ulonglong2 *p = reinterpret_cast<const ulonglong2 *>(wrow);
#pragma unroll
    for (int q = 0; q < 16; ++q) {
        ulonglong2 w = p[q];
        fma2(a[2 * q + 0], w.x, xx);
        fma2(a[2 * q + 1], w.y, xx);
    }
}

// Shared layout (floats): [0,19456) W0 | [19456,23552) W1 | [23552,27648) W2 | [27648,27904) W3
// Then: 14 u32 PH table (+pad), then 64KB point-2 activation spill (256 x 32 u64).
#define SW1_OFF 19456
#define SW2_OFF 23552
#define SW3_OFF 27648
#define SMEM_FLOATS 27904
#define SH2_BYTE_OFF (SMEM_FLOATS * 4 + 64)   // 111680, 8B aligned
#define SMEM_BYTES (SH2_BYTE_OFF + 256 * 32 * 8)

// ---- Payne-Hanek-style window state: one per (point, dim) ------------------
struct PH {
    u64 Ghi, Glo, m64;
    unsigned negmask;  // 0 or 0xFFFFFFFF (sign of a); folded into r32 (exact)
};
__device__ __forceinline__ PH ph_prep(float xn, const unsigned *sPH) {
    PH S;
    const float a = __fmul_rn(xn, 3.14159274101257324f); // a = fl(x * pi_f32)
    unsigned ab = __float_as_uint(a);
    S.negmask = (ab & 0x80000000u) ? 0xFFFFFFFFu : 0u;
    ab &= 0x7FFFFFFFu;
    int e = (int)(ab >> 23);
    unsigned m = ab & 0x007FFFFFu;
    if (e) m |= 0x00800000u; else e = 1;  // denormal: a = m * 2^(1-150)
    const int p0 = e + 10;                // window start bit in padded stream
    int wq = p0 >> 5;
    const int rr = p0 & 31;
    wq = min(wq, 8);
    const u64 A = ((u64)sPH[wq] << 32) | sPH[wq + 1];
    const u64 B = ((u64)sPH[wq + 2] << 32) | sPH[wq + 3];
    const u64 C = ((u64)sPH[wq + 4] << 32) | sPH[wq + 5];
    if (rr) {
        S.Ghi = (A << rr) | (B >> (64 - rr));
        S.Glo = (B << rr) | (C >> (64 - rr));
    } else {
        S.Ghi = A; S.Glo = B;
    }
    S.m64 = (u64)m;
    return S;
}
// One step: emit sin/cos(2^k * a), advance window by one bit (k -> k+1).
// r32 = top 32 bits of frac (centered); angle = 2*pi * r32 / 2^32.
// Sign of a folded by exact integer negation (sin odd, cos even).
__device__ __forceinline__ void ph_step(PH &S, float &s, float &c) {
    const u64 fr = S.m64 * S.Ghi;               // frac(m*G), Q0.64
    int r32 = (int)(unsigned)(fr >> 32);        // centered top 32 bits
    r32 = (int)(((unsigned)r32 ^ S.negmask) - S.negmask);
    const float ang = (float)r32 * 1.4629180792671596e-9f; // * 2pi/2^32
    __sincosf(ang, &s, &c);                     // |ang| <= pi: fast+accurate
    S.Ghi = (S.Ghi << 1) | (S.Glo >> 63);
    S.Glo <<= 1;
}

// Triplane bilinear gather -> 16 features (summed over 3 planes).
__device__ __forceinline__ void gather_feats(const float *__restrict__ tri,
                                             float sc0, float sc1, float sc2,
                                             float *f) {
#pragma unroll
    for (int j = 0; j < 16; ++j) f[j] = 0.f;
    const float scv[3] = {sc0, sc1, sc2};
#pragma unroll
    for (int p = 0; p < 3; ++p) {
        const float cx = (p == 2) ? scv[1] : scv[0];
        const float cy = (p == 0) ? scv[1] : scv[2];
        const float gx = (cx + 1.f) * 0.5f * 31.f;
        const float gy = (cy + 1.f) * 0.5f * 31.f;
        const float x0f = fminf(fmaxf(floorf(gx), 0.f), 31.f);
        const float y0f = fminf(fmaxf(floorf(gy), 0.f), 31.f);
        const int x0 = (int)x0f, y0 = (int)y0f;
        const int x1 = min(x0 + 1, 31), y1 = min(y0 + 1, 31);
        const float wx = gx - x0f, wy = gy - y0f;
        const float w00 = (1.f - wx) * (1.f - wy);
        const float w01 = wx * (1.f - wy);
        const float w10 = (1.f - wx) * wy;
        const float w11 = wx * wy;
        const float *bp = tri + p * 16384;
        const float4 *c00 = (const float4 *)(bp + (y0 * 32 + x0) * 16);
        const float4 *c01 = (const float4 *)(bp + (y0 * 32 + x1) * 16);
        const float4 *c10 = (const float4 *)(bp + (y1 * 32 + x0) * 16);
        const float4 *c11 = (const float4 *)(bp + (y1 * 32 + x1) * 16);
#pragma unroll
        for (int j = 0; j < 4; ++j) {
            const float4 v00 = c00[j], v01 = c01[j], v10 = c10[j], v11 = c11[j];
            f[4 * j + 0] += v00.x * w00 + v01.x * w01 + v10.x * w10 + v11.x * w11;
            f[4 * j + 1] += v00.y * w00 + v01.y * w01 + v10.y * w10 + v11.y * w11;
            f[4 * j + 2] += v00.z * w00 + v01.z * w01 + v10.z * w10 + v11.z * w11;
            f[4 * j + 3] += v00.w * w00 + v01.w * w01 + v10.w * w10 + v11.w * w11;
        }
    }
}

// One 64->64 hidden layer + sin activation for points (0,1) packed by point.
// Two 32-output half-passes bound register pressure (~224 peak).
__device__ __forceinline__ void hidden_layer2(u64 *hp, const float *Ws) {
    u64 done[32];
    // ---- half 0: outputs 0..31 ----
    {
        u64 b0[16], b1[16];
#pragma unroll
        for (int t = 0; t < 16; ++t) { b0[t] = 0ull; b1[t] = 0ull; }
#pragma unroll
        for (int i = 0; i < 64; ++i) {
            float lo, hi; unpack2(hp[i], lo, hi);
            const u64 x0 = dup2(lo), x1 = dup2(hi);
            const ulonglong2 *p = (const ulonglong2 *)(Ws + i * 64);
#pragma unroll
            for (int q = 0; q < 8; ++q) {
                ulonglong2 w = p[q];
                fma2(b0[2 * q + 0], w.x, x0);
                fma2(b0[2 * q + 1], w.y, x0);
                fma2(b1[2 * q + 0], w.x, x1);
                fma2(b1[2 * q + 1], w.y, x1);
            }
        }
#pragma unroll
        for (int t = 0; t < 16; ++t) {
            float a0l, a0h, a1l, a1h;
            unpack2(b0[t], a0l, a0h);
            unpack2(b1[t], a1l, a1h);
            done[2 * t + 0] = pack2(__sinf(a0l), __sinf(a1l));
            done[2 * t + 1] = pack2(__sinf(a0h), __sinf(a1h));
        }
    }
    // ---- half 1: outputs 32..63 ----
    {
        u64 b0[16], b1[16];
#pragma unroll
        for (int t = 0; t < 16; ++t) { b0[t] = 0ull; b1[t] = 0ull; }
#pragma unroll
        for (int i = 0; i < 64; ++i) {
            float lo, hi; unpack2(hp[i], lo, hi);
            const u64 x0 = dup2(lo), x1 = dup2(hi);
            const ulonglong2 *p = (const ulonglong2 *)(Ws + i * 64 + 32);
#pragma unroll
            for (int q = 0; q < 8; ++q) {
                ulonglong2 w = p[q];
                fma2(b0[2 * q + 0], w.x, x0);
                fma2(b0[2 * q + 1], w.y, x0);
                fma2(b1[2 * q + 0], w.x, x1);
                fma2(b1[2 * q + 1], w.y, x1);
            }
        }
#pragma unroll
        for (int t = 0; t < 16; ++t) {
            float a0l, a0h, a1l, a1h;
            unpack2(b0[t], a0l, a0h);
            unpack2(b1[t], a1l, a1h);
            hp[32 + 2 * t + 0] = pack2(__sinf(a0l), __sinf(a1l));
            hp[32 + 2 * t + 1] = pack2(__sinf(a0h), __sinf(a1h));
        }
    }
#pragma unroll
    for (int j = 0; j < 32; ++j) hp[j] = done[j];
}

// Single-point 64->64 hidden layer + sin, activations as 32 unit-pair u64s.
__device__ __forceinline__ void hidden_layer1(u64 *h2, const float *Ws) {
    u64 b[32];
#pragma unroll
    for (int t = 0; t < 32; ++t) b[t] = 0ull;
#pragma unroll
    for (int i = 0; i < 64; ++i) {
        float lo, hi; unpack2(h2[i >> 1], lo, hi);
        const u64 xx = dup2((i & 1) ? hi : lo);
        row_fma1(b, Ws + i * 64, xx);
    }
#pragma unroll
    for (int q = 0; q < 32; ++q) {
        float lo, hi; unpack2(b[q], lo, hi);
        h2[q] = pack2(__sinf(lo), __sinf(hi));
    }
}

__global__ void __launch_bounds__(256, 1)
tri_mlp_kernel(const float *__restrict__ pos, const float *__restrict__ aabb,
               const float *__restrict__ tri, const float *__restrict__ gW0,
               const float *__restrict__ gW1, const float *__restrict__ gW2,
               const float *__restrict__ gW3, float *__restrict__ out, int N)
{
    extern __shared__ float sW[];
    unsigned *sPH = (unsigned *)(sW + SMEM_FLOATS);
    u64 *sH2 = (u64 *)((char *)sW + SH2_BYTE_OFF);  // [q*256 + tid]
    const int tid = threadIdx.x;

    // Cooperative weight staging into shared
    {
        float4 *d0 = (float4 *)sW;                 const float4 *s0 = (const float4 *)gW0;
        for (int i = tid; i < 4864; i += 256) d0[i] = s0[i];
        float4 *d1 = (float4 *)(sW + SW1_OFF);     const float4 *s1 = (const float4 *)gW1;
        for (int i = tid; i < 1024; i += 256) d1[i] = s1[i];
        float4 *d2 = (float4 *)(sW + SW2_OFF);     const float4 *s2 = (const float4 *)gW2;
        for (int i = tid; i < 1024; i += 256) d2[i] = s2[i];
        float4 *d3 = (float4 *)(sW + SW3_OFF);     const float4 *s3 = (const float4 *)gW3;
        for (int i = tid; i < 64; i += 256) d3[i] = s3[i];
        if (tid < 14) sPH[tid] = c_PH[tid];
    }
    __syncthreads();

    // Three points per thread within a 768-point block tile.
    const int p0 = blockIdx.x * 768 + tid;
    if (p0 >= N) return;
    const int p1 = p0 + 256, p2 = p0 + 512;
    const bool v1 = (p1 < N), v2 = (p2 < N);
    const int i1 = v1 ? p1 : p0;
    const int i2 = v2 ? p2 : p0;

    const float mn0 = aabb[0], mn1 = aabb[1], mn2 = aabb[2];
    const float mx0 = aabb[3], mx1 = aabb[4], mx2 = aabb[5];

    const float ax = pos[p0 * 3 + 0], ay = pos[p0 * 3 + 1], az = pos[p0 * 3 + 2];
    const float bx = pos[i1 * 3 + 0], by = pos[i1 * 3 + 1], bz = pos[i1 * 3 + 2];
    const float cx = pos[i2 * 3 + 0], cy = pos[i2 * 3 + 1], cz = pos[i2 * 3 + 2];

    // IEEE-exact normalization (no contraction) to match reference bitwise
    const float xa0 = __fdiv_rn(__fsub_rn(ax, mn0), __fsub_rn(mx0, mn0));
    const float xa1 = __fdiv_rn(__fsub_rn(ay, mn1), __fsub_rn(mx1, mn1));
    const float xa2 = __fdiv_rn(__fsub_rn(az, mn2), __fsub_rn(mx2, mn2));
    const float xb0 = __fdiv_rn(__fsub_rn(bx, mn0), __fsub_rn(mx0, mn0));
    const float xb1 = __fdiv_rn(__fsub_rn(by, mn1), __fsub_rn(mx1, mn1));
    const float xb2 = __fdiv_rn(__fsub_rn(bz, mn2), __fsub_rn(mx2, mn2));
    const float xc0 = __fdiv_rn(__fsub_rn(cx, mn0), __fsub_rn(mx0, mn0));
    const float xc1 = __fdiv_rn(__fsub_rn(cy, mn1), __fsub_rn(mx1, mn1));
    const float xc2 = __fdiv_rn(__fsub_rn(cz, mn2), __fsub_rn(mx2, mn2));
    const bool sel0 = (xa0 > 0.f) && (xa0 < 1.f) && (xa1 > 0.f) && (xa1 < 1.f) &&
                      (xa2 > 0.f) && (xa2 < 1.f);
    const bool sel1 = (xb0 > 0.f) && (xb0 < 1.f) && (xb1 > 0.f) && (xb1 < 1.f) &&
                      (xb2 > 0.f) && (xb2 < 1.f);
    const bool sel2 = (xc0 > 0.f) && (xc0 < 1.f) && (xc1 > 0.f) && (xc1 < 1.f) &&
                      (xc2 > 0.f) && (xc2 < 1.f);

    // ---------------- Layer 0 accumulation (streamed features) --------------
    u64 acc0[32], acc1[32], acc2[32];
#pragma unroll
    for (int q = 0; q < 32; ++q) { acc0[q] = 0ull; acc1[q] = 0ull; acc2[q] = 0ull; }

    const float xav[3] = {xa0, xa1, xa2};
    const float xbv[3] = {xb0, xb1, xb2};
    const float xcv[3] = {xc0, xc1, xc2};

#pragma unroll
    for (int d = 0; d < 3; ++d) {
        PH S0 = ph_prep(xav[d], sPH);
        PH S1 = ph_prep(xbv[d], sPH);
        PH S2 = ph_prep(xcv[d], sPH);
        const float *wrow = sW + d * 96 * 64;
#pragma unroll 2
        for (int k = 0; k < 48; ++k) {
            float s0, c0, s1, c1, s2, c2;
            ph_step(S0, s0, c0);
            ph_step(S1, s1, c1);
            ph_step(S2, s2, c2);
            row_fma3(acc0, acc1, acc2, wrow, dup2(s0), dup2(s1), dup2(s2)); wrow += 64;
            row_fma3(acc0, acc1, acc2, wrow, dup2(c0), dup2(c1), dup2(c2)); wrow += 64;
        }
    }

    // Triplane bilinear features (L2-resident table)
    {
        float f0[16], f1[16], f2[16];
        gather_feats(tri, 2.f * xa0 - 1.f, 2.f * xa1 - 1.f, 2.f * xa2 - 1.f, f0);
        gather_feats(tri, 2.f * xb0 - 1.f, 2.f * xb1 - 1.f, 2.f * xb2 - 1.f, f1);
        gather_feats(tri, 2.f * xc0 - 1.f, 2.f * xc1 - 1.f, 2.f * xc2 - 1.f, f2);
#pragma unroll
        for (int t = 0; t < 16; ++t)
            row_fma3(acc0, acc1, acc2, sW + (288 + t) * 64,
                     dup2(f0[t]), dup2(f1[t]), dup2(f2[t]));
    }

    // Point 2: sin activation, spill to shared (frees 64 regs for pass A)
#pragma unroll
    for (int q = 0; q < 32; ++q) {
        float lo, hi; unpack2(acc2[q], lo, hi);
        sH2[q * 256 + tid] = pack2(__sinf(lo), __sinf(hi));
    }

    // Points 0,1: sin activation; repack as (point0, point1) per hidden unit
    u64 hp[64];
#pragma unroll
    for (int q = 0; q < 32; ++q) {
        float a0l, a0h, a1l, a1h;
        unpack2(acc0[q], a0l, a0h);
        unpack2(acc1[q], a1l, a1h);
        hp[2 * q + 0] = pack2(__sinf(a0l), __sinf(a1l));
        hp[2 * q + 1] = pack2(__sinf(a0h), __sinf(a1h));
    }

    // ---------------- Pass A: hidden + output for points 0,1 ----------------
    hidden_layer2(hp, sW + SW1_OFF);
    hidden_layer2(hp, sW + SW2_OFF);

    {
        u64 oa01 = 0ull, oa23 = 0ull, ob01 = 0ull, ob23 = 0ull;
        const float *W3s = sW + SW3_OFF;
#pragma unroll
        for (int i = 0; i < 64; ++i) {
            float lo, hi; unpack2(hp[i], lo, hi);
            const u64 x0 = dup2(lo), x1 = dup2(hi);
            const ulonglong2 w = *(const ulonglong2 *)(W3s + i * 4);
            fma2(oa01, w.x, x0);
            fma2(oa23, w.y, x0);
            fma2(ob01, w.x, x1);
            fma2(ob23, w.y, x1);
        }
        float o0, o1, o2, o3;
        unpack2(oa01, o0, o1);
        unpack2(oa23, o2, o3);
        out[p0 * 3 + 0] = 1.f / (1.f + __expf(-o0));
        out[p0 * 3 + 1] = 1.f / (1.f + __expf(-o1));
        out[p0 * 3 + 2] = 1.f / (1.f + __expf(-o2));
        out[3 * N + p0] = sel0 ? __expf(o3 - 1.f) : 0.f;
        if (v1) {
            unpack2(ob01, o0, o1);
            unpack2(ob23, o2, o3);
            out[p1 * 3 + 0] = 1.f / (1.f + __expf(-o0));
            out[p1 * 3 + 1] = 1.f / (1.f + __expf(-o1));
            out[p1 * 3 + 2] = 1.f / (1.f + __expf(-o2));
            out[3 * N + p1] = sel1 ? __expf(o3 - 1.f) : 0.f;
        }
    }

    // ---------------- Pass B: hidden + output for point 2 -------------------
    {
        u64 h2[32];
#pragma unroll
        for (int q = 0; q < 32; ++q) h2[q] = sH2[q * 256 + tid];

        hidden_layer1(h2, sW + SW1_OFF);
        hidden_layer1(h2, sW + SW2_OFF);

        u64 oc01 = 0ull, oc23 = 0ull;
        const float *W3s = sW + SW3_OFF;
#pragma unroll
        for (int i = 0; i < 64; ++i) {
            float lo, hi; unpack2(h2[i >> 1], lo, hi);
            const u64 xx = dup2((i & 1) ? hi : lo);
            const ulonglong2 w = *(const ulonglong2 *)(W3s + i * 4);
            fma2(oc01, w.x, xx);
            fma2(oc23, w.y, xx);
        }
        if (v2) {
            float o0, o1, o2, o3;
            unpack2(oc01, o0, o1);
            unpack2(oc23, o2, o3);
            out[p2 * 3 + 0] = 1.f / (1.f + __expf(-o0));
            out[p2 * 3 + 1] = 1.f / (1.f + __expf(-o1));
            out[p2 * 3 + 2] = 1.f / (1.f + __expf(-o2));
            out[3 * N + p2] = sel2 ? __expf(o3 - 1.f) : 0.f;
        }
    }
}

extern "C" void kernel_launch(void *const *d_in, const int *in_sizes, int n_in,
                              void *d_out, int out_size)
{
    const float *positions = (const float *)d_in[0];
    const float *aabb      = (const float *)d_in[1];
    const float *tri       = (const float *)d_in[2];
    const float *W0        = (const float *)d_in[3];
    const float *W1        = (const float *)d_in[4];
    const float *W2        = (const float *)d_in[5];
    const float *W3        = (const float *)d_in[6];
    float *out = (float *)d_out;
    const int N = in_sizes[0] / 3;

    static bool attr_set = false;
    if (!attr_set) {
        cudaFuncSetAttribute(tri_mlp_kernel,
                             cudaFuncAttributeMaxDynamicSharedMemorySize,
                             SMEM_BYTES);
        attr_set = true;
    }

    const int blocks = (N + 767) / 768;
    tri_mlp_kernel<<<blocks, 256, SMEM_BYTES>>>(positions, aabb, tri, W0, W1,
                                                W2, W3, out, N);
}